// round 1
// baseline (speedup 1.0000x reference)
#include <cuda_runtime.h>

#define BB 128
#define TT 1000
#define NN 1024
#define ALPHA_C 0.995f
#define VTH_C 2.0f

// scratch: drive matrix stored transposed [T, B] so the scan reads coalesced
__device__ float g_drive[TT * BB];

// ---------------------------------------------------------------------------
// Kernel 1: drive[b,t] = dot(x[b,t,:], w)   (HBM-bound streaming GEMV)
// one warp per row, w held in 32 registers per lane, grid-stride over rows
// ---------------------------------------------------------------------------
__global__ void __launch_bounds__(256) lif_gemv_kernel(
    const float* __restrict__ x, const float* __restrict__ w) {
    const int lane  = threadIdx.x & 31;
    const int warp  = (blockIdx.x * blockDim.x + threadIdx.x) >> 5;
    const int nwarp = (gridDim.x * blockDim.x) >> 5;

    // load w once: element pattern lane + 32*k (float4 granularity), 8 vec4 = 32 floats
    const float4* __restrict__ w4 = (const float4*)w;
    float4 wr[8];
#pragma unroll
    for (int k = 0; k < 8; k++) wr[k] = w4[lane + 32 * k];

    const int R = BB * TT;  // 128000 rows
    for (int r = warp; r < R; r += nwarp) {
        const float4* __restrict__ x4 = (const float4*)(x + (size_t)r * NN);
        float s = 0.0f;
#pragma unroll
        for (int k = 0; k < 8; k++) {           // 8 independent 16B loads -> MLP 8
            float4 xv = x4[lane + 32 * k];
            s += xv.x * wr[k].x;
            s += xv.y * wr[k].y;
            s += xv.z * wr[k].z;
            s += xv.w * wr[k].w;
        }
#pragma unroll
        for (int off = 16; off > 0; off >>= 1)
            s += __shfl_xor_sync(0xffffffffu, s, off);
        if (lane == 0) {
            int b = r / TT;
            int t = r - b * TT;
            g_drive[t * BB + b] = s;            // transposed store
        }
    }
}

// ---------------------------------------------------------------------------
// Kernel 2: sequential LIF scan, one thread per batch element (128 chains)
//   v_t = alpha*v + d_t - vth*z_{t-1};  z_t = (v_t - vth > 0)
// unroll 4, buffered float4 stores. d_out = [v_seq (B,T) | z_seq (B,T)]
// ---------------------------------------------------------------------------
__global__ void __launch_bounds__(128) lif_scan_kernel(float* __restrict__ out) {
    const int b = threadIdx.x;
    float v = 0.0f, z = 0.0f;
    float* __restrict__ vout = out + (size_t)b * TT;
    float* __restrict__ zout = out + (size_t)BB * TT + (size_t)b * TT;

    for (int t0 = 0; t0 < TT; t0 += 4) {
        // coalesced loads across the 128 threads, independent of the chain
        float d0 = g_drive[(t0 + 0) * BB + b];
        float d1 = g_drive[(t0 + 1) * BB + b];
        float d2 = g_drive[(t0 + 2) * BB + b];
        float d3 = g_drive[(t0 + 3) * BB + b];

        float4 vv, zz;
        v = ALPHA_C * v + d0 - VTH_C * z;  z = (v - VTH_C > 0.0f) ? 1.0f : 0.0f;
        vv.x = v; zz.x = z;
        v = ALPHA_C * v + d1 - VTH_C * z;  z = (v - VTH_C > 0.0f) ? 1.0f : 0.0f;
        vv.y = v; zz.y = z;
        v = ALPHA_C * v + d2 - VTH_C * z;  z = (v - VTH_C > 0.0f) ? 1.0f : 0.0f;
        vv.z = v; zz.z = z;
        v = ALPHA_C * v + d3 - VTH_C * z;  z = (v - VTH_C > 0.0f) ? 1.0f : 0.0f;
        vv.w = v; zz.w = z;

        *(float4*)(vout + t0) = vv;   // b*1000*4B and t0*4B are 16B-aligned
        *(float4*)(zout + t0) = zz;
    }
}

extern "C" void kernel_launch(void* const* d_in, const int* in_sizes, int n_in,
                              void* d_out, int out_size) {
    const float* x = (const float*)d_in[0];   // [B, T, N] f32
    const float* w = (const float*)d_in[1];   // [N] f32
    float* out = (float*)d_out;               // [2, B, T] f32 (v then z)

    // 592 blocks x 256 thr = 4736 warps -> ~27 rows/warp (amortizes w-in-regs)
    lif_gemv_kernel<<<592, 256>>>(x, w);
    lif_scan_kernel<<<1, 128>>>(out);         // same stream: serializes after gemv
}

// round 2
// speedup vs baseline: 1.1358x; 1.1358x over previous
#include <cuda_runtime.h>

#define BB 128
#define TT 1000
#define NN 1024
#define ALPHA_C 0.995f
#define VTH_C 2.0f

#define CHUNK 100          // timesteps per smem chunk (10 chunks total)
#define NCHUNK (TT / CHUNK)

// scratch: drive matrix stored transposed [T, B] so the scan reads coalesced
__device__ float g_drive[TT * BB];

// ---------------------------------------------------------------------------
// Kernel 1: drive[b,t] = dot(x[b,t,:], w)   (HBM-bound streaming GEMV)
// one warp per row, w held in 32 registers per lane, grid-stride over rows
// ---------------------------------------------------------------------------
__global__ void __launch_bounds__(256) lif_gemv_kernel(
    const float* __restrict__ x, const float* __restrict__ w) {
    const int lane  = threadIdx.x & 31;
    const int warp  = (blockIdx.x * blockDim.x + threadIdx.x) >> 5;
    const int nwarp = (gridDim.x * blockDim.x) >> 5;

    const float4* __restrict__ w4 = (const float4*)w;
    float4 wr[8];
#pragma unroll
    for (int k = 0; k < 8; k++) wr[k] = w4[lane + 32 * k];

    const int R = BB * TT;  // 128000 rows
    for (int r = warp; r < R; r += nwarp) {
        const float4* __restrict__ x4 = (const float4*)(x + (size_t)r * NN);
        float s = 0.0f;
#pragma unroll
        for (int k = 0; k < 8; k++) {           // 8 independent 16B loads -> MLP 8
            float4 xv = x4[lane + 32 * k];
            s += xv.x * wr[k].x;
            s += xv.y * wr[k].y;
            s += xv.z * wr[k].z;
            s += xv.w * wr[k].w;
        }
#pragma unroll
        for (int off = 16; off > 0; off >>= 1)
            s += __shfl_xor_sync(0xffffffffu, s, off);
        if (lane == 0) {
            int b = r / TT;
            int t = r - b * TT;
            g_drive[t * BB + b] = s;            // transposed store
        }
    }
}

// ---------------------------------------------------------------------------
// cp.async helpers (16B LDGSTS)
// ---------------------------------------------------------------------------
__device__ __forceinline__ void cp_async16(void* smem_dst, const void* gmem_src) {
    unsigned saddr = (unsigned)__cvta_generic_to_shared(smem_dst);
    asm volatile("cp.async.ca.shared.global [%0], [%1], 16;\n"
                 :: "r"(saddr), "l"(gmem_src) : "memory");
}
__device__ __forceinline__ void cp_async_commit() {
    asm volatile("cp.async.commit_group;\n" ::: "memory");
}
template <int N>
__device__ __forceinline__ void cp_async_wait() {
    asm volatile("cp.async.wait_group %0;\n" :: "n"(N) : "memory");
}

// ---------------------------------------------------------------------------
// Kernel 2: sequential LIF scan, one thread per batch element (128 chains).
// Drive is staged through a double-buffered smem pipeline (cp.async) so the
// L2 load latency is hidden behind the 100-step dependent compute per chunk.
//   v_t = alpha*v + d_t - vth*z_{t-1};  z_t = (v_t - vth > 0)
// d_out = [v_seq (B,T) | z_seq (B,T)]
// ---------------------------------------------------------------------------
__global__ void __launch_bounds__(128) lif_scan_kernel(float* __restrict__ out) {
    __shared__ float sd[2][CHUNK * BB];      // 2 x 50 KB

    const int tid = threadIdx.x;
    const int b = tid;
    // per-chunk copy: CHUNK*BB floats = 3200 float4, 128 threads -> 25 each
    const int F4_PER_CHUNK = CHUNK * BB / 4; // 3200

    // prologue: stage chunk 0
    {
        const float4* src = (const float4*)(g_drive);
#pragma unroll
        for (int k = 0; k < F4_PER_CHUNK / 128; k++)
            cp_async16(&((float4*)sd[0])[tid + 128 * k], &src[tid + 128 * k]);
        cp_async_commit();
    }

    float v = 0.0f, z = 0.0f;
    float* __restrict__ vout = out + (size_t)b * TT;
    float* __restrict__ zout = out + (size_t)BB * TT + (size_t)b * TT;

    for (int c = 0; c < NCHUNK; c++) {
        // issue copy of next chunk into the other buffer
        if (c + 1 < NCHUNK) {
            const float4* src = (const float4*)(g_drive + (c + 1) * CHUNK * BB);
            float4* dst = (float4*)sd[(c + 1) & 1];
#pragma unroll
            for (int k = 0; k < F4_PER_CHUNK / 128; k++)
                cp_async16(&dst[tid + 128 * k], &src[tid + 128 * k]);
            cp_async_commit();
            cp_async_wait<1>();   // current chunk's group done
        } else {
            cp_async_wait<0>();
        }
        __syncthreads();

        const float* __restrict__ d = sd[c & 1];
        const int tbase = c * CHUNK;
#pragma unroll
        for (int i = 0; i < CHUNK; i += 4) {
            float4 vv, zz;
            float d0 = d[(i + 0) * BB + b];
            float d1 = d[(i + 1) * BB + b];
            float d2 = d[(i + 2) * BB + b];
            float d3 = d[(i + 3) * BB + b];

            v = fmaf(ALPHA_C, v, fmaf(-VTH_C, z, d0));
            z = (v > VTH_C) ? 1.0f : 0.0f;  vv.x = v; zz.x = z;
            v = fmaf(ALPHA_C, v, fmaf(-VTH_C, z, d1));
            z = (v > VTH_C) ? 1.0f : 0.0f;  vv.y = v; zz.y = z;
            v = fmaf(ALPHA_C, v, fmaf(-VTH_C, z, d2));
            z = (v > VTH_C) ? 1.0f : 0.0f;  vv.z = v; zz.z = z;
            v = fmaf(ALPHA_C, v, fmaf(-VTH_C, z, d3));
            z = (v > VTH_C) ? 1.0f : 0.0f;  vv.w = v; zz.w = z;

            *(float4*)(vout + tbase + i) = vv;
            *(float4*)(zout + tbase + i) = zz;
        }
        __syncthreads();   // buffer (c&1) may be overwritten two iters later
    }
}

extern "C" void kernel_launch(void* const* d_in, const int* in_sizes, int n_in,
                              void* d_out, int out_size) {
    const float* x = (const float*)d_in[0];   // [B, T, N] f32
    const float* w = (const float*)d_in[1];   // [N] f32
    float* out = (float*)d_out;               // [2, B, T] f32 (v then z)

    lif_gemv_kernel<<<592, 256>>>(x, w);
    lif_scan_kernel<<<1, 128>>>(out);         // same stream: serializes after gemv
}

// round 3
// speedup vs baseline: 1.4473x; 1.2743x over previous
#include <cuda_runtime.h>

#define BB 128
#define TT 1000
#define NN 1024
#define ALPHA_C 0.995f
#define VTH_C 2.0f

#define SCB 4                 // scan blocks
#define CPB (BB / SCB)        // chains per block = 32
#define CHUNK 50              // timesteps per smem chunk
#define NCHUNK (TT / CHUNK)   // 20
#define PAD (CHUNK + 1)       // 51, conflict-free staging stride

// drive scratch, block-major: [SCB][TT][CPB]
__device__ float g_drive[SCB * TT * CPB];

// ---------------------------------------------------------------------------
// Kernel 1: drive = x @ w, HBM-bound streaming GEMV (warp per row)
// ---------------------------------------------------------------------------
__global__ void __launch_bounds__(256) lif_gemv_kernel(
    const float* __restrict__ x, const float* __restrict__ w) {
    const int lane  = threadIdx.x & 31;
    const int warp  = (blockIdx.x * blockDim.x + threadIdx.x) >> 5;
    const int nwarp = (gridDim.x * blockDim.x) >> 5;

    const float4* __restrict__ w4 = (const float4*)w;
    float4 wr[8];
#pragma unroll
    for (int k = 0; k < 8; k++) wr[k] = w4[lane + 32 * k];

    const int R = BB * TT;
    for (int r = warp; r < R; r += nwarp) {
        const float4* __restrict__ x4 = (const float4*)(x + (size_t)r * NN);
        float s = 0.0f;
#pragma unroll
        for (int k = 0; k < 8; k++) {
            float4 xv = x4[lane + 32 * k];
            s += xv.x * wr[k].x;
            s += xv.y * wr[k].y;
            s += xv.z * wr[k].z;
            s += xv.w * wr[k].w;
        }
#pragma unroll
        for (int off = 16; off > 0; off >>= 1)
            s += __shfl_xor_sync(0xffffffffu, s, off);
        if (lane == 0) {
            int b = r / TT;
            int t = r - b * TT;
            // block-major layout for the scan kernel
            g_drive[(b >> 5) * (TT * CPB) + t * CPB + (b & 31)] = s;
        }
    }
}

// ---------------------------------------------------------------------------
// cp.async helpers
// ---------------------------------------------------------------------------
__device__ __forceinline__ void cp_async16(void* smem_dst, const void* gmem_src) {
    unsigned saddr = (unsigned)__cvta_generic_to_shared(smem_dst);
    asm volatile("cp.async.ca.shared.global [%0], [%1], 16;\n"
                 :: "r"(saddr), "l"(gmem_src) : "memory");
}
__device__ __forceinline__ void cp_async_commit() {
    asm volatile("cp.async.commit_group;\n" ::: "memory");
}
template <int N>
__device__ __forceinline__ void cp_async_wait() {
    asm volatile("cp.async.wait_group %0;\n" :: "n"(N) : "memory");
}

// ---------------------------------------------------------------------------
// Kernel 2: LIF scan. grid = 4 blocks x 128 threads; 32 chains per block.
// Warp 0 runs the chains; v/z staged into padded smem [chain][t]; all 128
// threads then write out coalesced. Drive double-buffered via cp.async.
// Chain per step: FSETP -> FSEL(d-vth, d) -> FFMA  (~12 cyc).
// ---------------------------------------------------------------------------
__global__ void __launch_bounds__(128) lif_scan_kernel(float* __restrict__ out) {
    __shared__ float sd[2][CHUNK * CPB];   // 2 x 6.4 KB drive staging [t][chain]
    __shared__ float sv[CPB * PAD];        // 6.5 KB, [chain][t] padded
    __shared__ float sz[CPB * PAD];

    const int tid = threadIdx.x;
    const int blk = blockIdx.x;
    const int b0  = blk * CPB;

    const float4* __restrict__ gsrc =
        (const float4*)(g_drive + (size_t)blk * TT * CPB);
    const int F4C = CHUNK * CPB / 4;       // 400 float4 per chunk

    // prologue: stage chunk 0
#pragma unroll
    for (int k = 0; k < 4; k++) {
        int idx = tid + 128 * k;
        if (idx < F4C) cp_async16(&((float4*)sd[0])[idx], &gsrc[idx]);
    }
    cp_async_commit();

    float v = 0.0f;
    bool  p = false;                        // z_{t-1} as predicate

    for (int c = 0; c < NCHUNK; c++) {
        if (c + 1 < NCHUNK) {
            const float4* src = gsrc + (c + 1) * F4C;
            float4* dst = (float4*)sd[(c + 1) & 1];
#pragma unroll
            for (int k = 0; k < 4; k++) {
                int idx = tid + 128 * k;
                if (idx < F4C) cp_async16(&dst[idx], &src[idx]);
            }
            cp_async_commit();
            cp_async_wait<1>();
        } else {
            cp_async_wait<0>();
        }
        __syncthreads();                    // chunk c staged; sv/sz free

        if (tid < CPB) {
            const float* __restrict__ d = sd[c & 1];
#pragma unroll
            for (int i = 0; i < CHUNK; i++) {
                float dd = d[i * CPB + tid];       // off-chain LDS
                float w1 = dd - VTH_C;             // off-chain FADD
                v = fmaf(ALPHA_C, v, p ? w1 : dd); // FSEL + FFMA on chain
                p = (v > VTH_C);                   // FSETP on chain
                sv[tid * PAD + i] = v;
                sz[tid * PAD + i] = p ? 1.0f : 0.0f;
            }
        }
        __syncthreads();                    // staging complete

        // coalesced writeout: flat over [chain][t], consecutive lanes -> consecutive t
        const int tbase = c * CHUNK;
        float* __restrict__ vo = out + (size_t)b0 * TT + tbase;
        float* __restrict__ zo = vo + (size_t)BB * TT;
#pragma unroll
        for (int k = 0; k < 13; k++) {
            int idx = tid + 128 * k;        // 0..1599
            if (idx < CHUNK * CPB) {
                int bb = idx / CHUNK;
                int ii = idx - bb * CHUNK;
                vo[(size_t)bb * TT + ii] = sv[bb * PAD + ii];
                zo[(size_t)bb * TT + ii] = sz[bb * PAD + ii];
            }
        }
        // next iteration's top __syncthreads orders writeout before sv/sz reuse
    }
}

extern "C" void kernel_launch(void* const* d_in, const int* in_sizes, int n_in,
                              void* d_out, int out_size) {
    const float* x = (const float*)d_in[0];   // [B, T, N] f32
    const float* w = (const float*)d_in[1];   // [N] f32
    float* out = (float*)d_out;               // [2, B, T] f32 (v then z)

    lif_gemv_kernel<<<592, 256>>>(x, w);
    lif_scan_kernel<<<SCB, 128>>>(out);
}